// round 8
// baseline (speedup 1.0000x reference)
#include <cuda_runtime.h>

// SSIM loss, single fused kernel, f32x2-packed blurs, GMEM-direct 8-wide horizontal pass.
// Shapes fixed: (16,31,256,256) fp32 x2 inputs, scalar fp32 out.

#define IMG   256
#define OUT   246          // 256 - 11 + 1
#define TW    32
#define TH    64
#define HALO  10
#define IN_H  74           // TH + HALO
#define PADH  36           // row stride (elems), moment arrays
#define NIMG  496
#define GX    8
#define GY    4
#define NBLOCKS (GX * GY * NIMG)   // 15872
#define NTOT  30015936.0   // 496 * 246 * 246

#define HM_B   (IN_H * PADH * 8)             // 21312
#define HM4_B  (IN_H * PADH * 4)             // 10656
#define SMEM_B (2 * HM_B + HM4_B)            // 53280

typedef unsigned long long u64;

__device__ constexpr float GW[11] = {
    0.00102838f, 0.00759874f, 0.03600078f, 0.10936071f, 0.21300555f,
    0.26601174f,
    0.21300555f, 0.10936071f, 0.03600078f, 0.00759874f, 0.00102838f
};

#define C1 1.0e-4f
#define C2 9.0e-4f

// ---- packed f32x2 helpers ----
__device__ __forceinline__ u64 pk2(float x, float y) {
    u64 r; asm("mov.b64 %0, {%1, %2};" : "=l"(r) : "f"(x), "f"(y)); return r;
}
__device__ __forceinline__ void unpk(u64 p, float& x, float& y) {
    asm("mov.b64 {%0, %1}, %2;" : "=f"(x), "=f"(y) : "l"(p));
}
__device__ __forceinline__ u64 f2fma(u64 a, u64 b, u64 c) {
    u64 d; asm("fma.rn.f32x2 %0, %1, %2, %3;" : "=l"(d) : "l"(a), "l"(b), "l"(c)); return d;
}
__device__ __forceinline__ u64 f2mul(u64 a, u64 b) {
    u64 d; asm("mul.rn.f32x2 %0, %1, %2;" : "=l"(d) : "l"(a), "l"(b)); return d;
}

__device__ double   g_acc;      // zero-init; each call leaves it back at 0
__device__ unsigned g_ticket;   // wraps back to 0 every call

// 8-output horizontal run over inputs k=0..17 (window cols gc..gc+17), streamed
// in 5 float4 chunks. Weight pairs use symmetry: only 6 distinct (12 regs).
template<bool FAST>
__device__ __forceinline__ void hrun(const float* __restrict__ xr,
                                     const float* __restrict__ yr,
                                     int gc, bool row_ok,
                                     u64* __restrict__ A, u64* __restrict__ B,
                                     float* __restrict__ S,
                                     const u64* __restrict__ W2h) {
    #pragma unroll
    for (int j = 0; j < 8; j++) { A[j] = 0; B[j] = 0; S[j] = 0.f; }

    #pragma unroll
    for (int cq = 0; cq < 5; cq++) {
        float4 x4, y4;
        if (FAST) {
            if (row_ok) {
                x4 = *(const float4*)(xr + 4 * cq);
                y4 = *(const float4*)(yr + 4 * cq);
            } else {
                x4 = make_float4(0.f, 0.f, 0.f, 0.f);
                y4 = make_float4(0.f, 0.f, 0.f, 0.f);
            }
        } else {
            float xt[4], yt[4];
            #pragma unroll
            for (int t = 0; t < 4; t++) {
                bool ok = row_ok && (gc + 4 * cq + t < IMG);
                xt[t] = ok ? xr[4 * cq + t] : 0.f;
                yt[t] = ok ? yr[4 * cq + t] : 0.f;
            }
            x4 = make_float4(xt[0], xt[1], xt[2], xt[3]);
            y4 = make_float4(yt[0], yt[1], yt[2], yt[3]);
        }
        const float* xs = &x4.x;
        const float* ys = &y4.x;
        #pragma unroll
        for (int t = 0; t < 4; t++) {
            const int k = 4 * cq + t;
            if (k >= 18) continue;                 // static prune
            float xk = xs[t], yk = ys[t];
            u64   p  = pk2(xk, yk);
            u64   sq = f2mul(p, p);
            float xy = xk * yk;
            #pragma unroll
            for (int j = 0; j < 8; j++) {
                const int kj = k - j;
                if (kj >= 0 && kj <= 10) {
                    const int wi = (kj <= 5) ? kj : 10 - kj;   // symmetry
                    A[j] = f2fma(p,  W2h[wi], A[j]);
                    B[j] = f2fma(sq, W2h[wi], B[j]);
                    S[j] = fmaf(GW[kj], xy, S[j]);             // imm-FFMA
                }
            }
        }
    }
}

__global__ __launch_bounds__(256, 4)
void ssim_main_kernel(const float* __restrict__ X, const float* __restrict__ Y,
                      float* __restrict__ out) {
    extern __shared__ __align__(16) unsigned char dsm[];
    u64   (*hm01)[PADH] = (u64  (*)[PADH]) dsm;
    u64   (*hm23)[PADH] = (u64  (*)[PADH])(dsm + HM_B);
    float (*hm4 )[PADH] = (float(*)[PADH])(dsm + 2 * HM_B);
    __shared__ float red[8];

    const int tid = threadIdx.x;
    const int C0  = blockIdx.x * TW;
    const int R0  = blockIdx.y * TH;
    const int img = blockIdx.z;

    const float* __restrict__ xi = X + (size_t)img * IMG * IMG;
    const float* __restrict__ yi = Y + (size_t)img * IMG * IMG;

    u64 W2h[6];
    #pragma unroll
    for (int k = 0; k < 6; k++) W2h[k] = pk2(GW[k], GW[k]);

    // ---- Phase 1: horizontal blur from GMEM. 74 rows x 4 runs of 8 outputs = 296 runs.
    const bool fastcol = (C0 + 43 < IMG);   // all 5 chunks in-bounds for every run
    for (int i = tid; i < IN_H * 4; i += 256) {
        const int r  = i >> 2;
        const int c0 = (i & 3) * 8;
        const int gr = R0 + r;
        const int gc = C0 + c0;
        const bool row_ok = (gr < IMG);
        const float* xr = xi + gr * IMG + gc;
        const float* yr = yi + gr * IMG + gc;

        u64 A[8], B[8]; float S[8];
        if (fastcol) hrun<true >(xr, yr, gc, row_ok, A, B, S, W2h);
        else         hrun<false>(xr, yr, gc, row_ok, A, B, S, W2h);

        *(ulonglong2*)&hm01[r][c0]     = make_ulonglong2(A[0], A[1]);
        *(ulonglong2*)&hm01[r][c0 + 2] = make_ulonglong2(A[2], A[3]);
        *(ulonglong2*)&hm01[r][c0 + 4] = make_ulonglong2(A[4], A[5]);
        *(ulonglong2*)&hm01[r][c0 + 6] = make_ulonglong2(A[6], A[7]);
        *(ulonglong2*)&hm23[r][c0]     = make_ulonglong2(B[0], B[1]);
        *(ulonglong2*)&hm23[r][c0 + 2] = make_ulonglong2(B[2], B[3]);
        *(ulonglong2*)&hm23[r][c0 + 4] = make_ulonglong2(B[4], B[5]);
        *(ulonglong2*)&hm23[r][c0 + 6] = make_ulonglong2(B[6], B[7]);
        *(float4*)&hm4[r][c0]     = make_float4(S[0], S[1], S[2], S[3]);
        *(float4*)&hm4[r][c0 + 4] = make_float4(S[4], S[5], S[6], S[7]);
    }
    __syncthreads();

    // ---- Phase 2: vertical blur (streaming, 8-output runs) + SSIM.
    const int c  = tid & 31;
    const int r0 = (tid >> 5) * 8;   // 0..56

    u64 acc01[8], acc23[8];
    float acc4[8];
    #pragma unroll
    for (int j = 0; j < 8; j++) { acc01[j] = 0; acc23[j] = 0; acc4[j] = 0.f; }

    #pragma unroll
    for (int k = 0; k < 18; k++) {
        u64 v = hm01[r0 + k][c];
        #pragma unroll
        for (int j = 0; j < 8; j++) {
            const int kj = k - j;
            if (kj >= 0 && kj <= 10) {
                const int wi = (kj <= 5) ? kj : 10 - kj;
                acc01[j] = f2fma(v, W2h[wi], acc01[j]);
            }
        }
    }
    #pragma unroll
    for (int k = 0; k < 18; k++) {
        u64 v = hm23[r0 + k][c];
        #pragma unroll
        for (int j = 0; j < 8; j++) {
            const int kj = k - j;
            if (kj >= 0 && kj <= 10) {
                const int wi = (kj <= 5) ? kj : 10 - kj;
                acc23[j] = f2fma(v, W2h[wi], acc23[j]);
            }
        }
    }
    #pragma unroll
    for (int k = 0; k < 18; k++) {
        float v = hm4[r0 + k][c];
        #pragma unroll
        for (int j = 0; j < 8; j++) {
            const int kj = k - j;
            if (kj >= 0 && kj <= 10) acc4[j] = fmaf(GW[kj], v, acc4[j]);
        }
    }

    float lsum = 0.f;
    const int oc = C0 + c;
    #pragma unroll
    for (int j = 0; j < 8; j++) {
        int orow = R0 + r0 + j;
        if (orow < OUT && oc < OUT) {
            float mx, my;   unpk(acc01[j], mx, my);
            float mxx, myy; unpk(acc23[j], mxx, myy);
            float mxy = acc4[j];
            float vx  = mxx - mx * mx;
            float vy  = myy - my * my;
            float cov = mxy - mx * my;
            float num = (2.f * mx * my + C1) * (2.f * cov + C2);
            float den = (mx * mx + my * my + C1) * (vx + vy + C2);
            lsum += __fdividef(num, den);
        }
    }

    // ---- block reduce -> global accumulator; last block finalizes + resets
    #pragma unroll
    for (int o = 16; o > 0; o >>= 1)
        lsum += __shfl_xor_sync(0xffffffffu, lsum, o);
    if ((tid & 31) == 0) red[tid >> 5] = lsum;
    __syncthreads();
    if (tid == 0) {
        float s = 0.f;
        #pragma unroll
        for (int w = 0; w < 8; w++) s += red[w];
        atomicAdd(&g_acc, (double)s);
        __threadfence();
        unsigned t = atomicInc(&g_ticket, NBLOCKS - 1);
        if (t == NBLOCKS - 1) {
            double tot = atomicAdd(&g_acc, 0.0);   // coherent read
            out[0] = (float)(1.0 - tot / NTOT);
            atomicExch((unsigned long long*)&g_acc, 0ull);  // reset for next call
        }
    }
}

extern "C" void kernel_launch(void* const* d_in, const int* in_sizes, int n_in,
                              void* d_out, int out_size) {
    const float* X = (const float*)d_in[0];
    const float* Y = (const float*)d_in[1];
    float* out = (float*)d_out;

    cudaFuncSetAttribute(ssim_main_kernel,
                         cudaFuncAttributeMaxDynamicSharedMemorySize, SMEM_B);

    dim3 grid(GX, GY, NIMG);   // 8 x 4 x 496
    ssim_main_kernel<<<grid, 256, SMEM_B>>>(X, Y, out);
}

// round 9
// speedup vs baseline: 1.0772x; 1.0772x over previous
#include <cuda_runtime.h>

// SSIM loss, single fused kernel, f32x2-packed blurs, GMEM-direct horizontal pass,
// interleaved moment layout + packed vertical hm4.
// Shapes fixed: (16,31,256,256) fp32 x2 inputs, scalar fp32 out.

#define IMG   256
#define OUT   246          // 256 - 11 + 1
#define TW    32
#define TH    64
#define HALO  10
#define IN_H  74           // TH + HALO
#define PADI  33           // row stride (ulonglong2 elems) for interleaved moments
#define PADH  36           // row stride (floats) for hm4
#define NIMG  496
#define GX    8
#define GY    4
#define NBLOCKS (GX * GY * NIMG)   // 15872
#define NTOT  30015936.0   // 496 * 246 * 246

#define HMI_B  (IN_H * PADI * 16)            // 39072
#define HM4_B  (IN_H * PADH * 4)             // 10656
#define SMEM_B (HMI_B + HM4_B)               // 49728

typedef unsigned long long u64;

__device__ constexpr float GW[11] = {
    0.00102838f, 0.00759874f, 0.03600078f, 0.10936071f, 0.21300555f,
    0.26601174f,
    0.21300555f, 0.10936071f, 0.03600078f, 0.00759874f, 0.00102838f
};

#define C1 1.0e-4f
#define C2 9.0e-4f

// ---- packed f32x2 helpers ----
__device__ __forceinline__ u64 pk2(float x, float y) {
    u64 r; asm("mov.b64 %0, {%1, %2};" : "=l"(r) : "f"(x), "f"(y)); return r;
}
__device__ __forceinline__ void unpk(u64 p, float& x, float& y) {
    asm("mov.b64 {%0, %1}, %2;" : "=f"(x), "=f"(y) : "l"(p));
}
__device__ __forceinline__ u64 f2fma(u64 a, u64 b, u64 c) {
    u64 d; asm("fma.rn.f32x2 %0, %1, %2, %3;" : "=l"(d) : "l"(a), "l"(b), "l"(c)); return d;
}
__device__ __forceinline__ u64 f2mul(u64 a, u64 b) {
    u64 d; asm("mul.rn.f32x2 %0, %1, %2;" : "=l"(d) : "l"(a), "l"(b)); return d;
}

__device__ double   g_acc;      // zero-init; each call leaves it back at 0
__device__ unsigned g_ticket;   // wraps back to 0 every call

__global__ __launch_bounds__(256, 4)
void ssim_main_kernel(const float* __restrict__ X, const float* __restrict__ Y,
                      float* __restrict__ out) {
    extern __shared__ __align__(16) unsigned char dsm[];
    ulonglong2 (*hmi)[PADI] = (ulonglong2(*)[PADI]) dsm;          // {.x={hx,hy}, .y={hxx,hyy}}
    float      (*hm4)[PADH] = (float     (*)[PADH])(dsm + HMI_B); // hxy
    __shared__ float red[8];

    const int tid = threadIdx.x;
    const int C0  = blockIdx.x * TW;
    const int R0  = blockIdx.y * TH;
    const int img = blockIdx.z;

    const float* __restrict__ xi = X + (size_t)img * IMG * IMG;
    const float* __restrict__ yi = Y + (size_t)img * IMG * IMG;

    // 6 distinct packed weight pairs (Gaussian symmetry: GW[k] == GW[10-k])
    u64 W2h[6];
    #pragma unroll
    for (int k = 0; k < 6; k++) W2h[k] = pk2(GW[k], GW[k]);

    // ---- Phase 1: horizontal blur from GMEM. 74 rows x 8 runs of 4 outputs.
    for (int i = tid; i < IN_H * 8; i += 256) {
        const int r  = i >> 3;
        const int c0 = (i & 7) * 4;
        const int gr = R0 + r;
        const int gc = C0 + c0;          // multiple of 4 -> 16B aligned

        float xv[16], yv[16];
        if (gr < IMG) {
            const float* __restrict__ xr = xi + gr * IMG + gc;
            const float* __restrict__ yr = yi + gr * IMG + gc;
            #pragma unroll
            for (int q = 0; q < 4; q++) {
                const int b = 4 * q;
                if (gc + b + 3 < IMG) {
                    float4 a = *(const float4*)(xr + b);
                    xv[b] = a.x; xv[b + 1] = a.y; xv[b + 2] = a.z; xv[b + 3] = a.w;
                    float4 d = *(const float4*)(yr + b);
                    yv[b] = d.x; yv[b + 1] = d.y; yv[b + 2] = d.z; yv[b + 3] = d.w;
                } else {
                    #pragma unroll
                    for (int t = 0; t < 4; t++) {
                        bool ok = (gc + b + t < IMG);
                        xv[b + t] = ok ? xr[b + t] : 0.f;
                        yv[b + t] = ok ? yr[b + t] : 0.f;
                    }
                }
            }
        } else {
            #pragma unroll
            for (int t = 0; t < 16; t++) { xv[t] = 0.f; yv[t] = 0.f; }
        }

        u64  A[4] = {0, 0, 0, 0};            // {hx,hy}
        u64  B[4] = {0, 0, 0, 0};            // {hxx,hyy}
        float S[4] = {0.f, 0.f, 0.f, 0.f};   // hxy
        #pragma unroll
        for (int k = 0; k < 14; k++) {
            u64   p  = pk2(xv[k], yv[k]);
            u64   sq = f2mul(p, p);
            float xy = xv[k] * yv[k];
            #pragma unroll
            for (int j = 0; j < 4; j++) {
                const int kj = k - j;
                if (kj >= 0 && kj <= 10) {
                    const int wi = (kj <= 5) ? kj : 10 - kj;   // symmetry
                    A[j] = f2fma(p,  W2h[wi], A[j]);
                    B[j] = f2fma(sq, W2h[wi], B[j]);
                    S[j] = fmaf(GW[kj], xy, S[j]);             // imm-FFMA
                }
            }
        }

        #pragma unroll
        for (int j = 0; j < 4; j++)
            hmi[r][c0 + j] = make_ulonglong2(A[j], B[j]);
        *(float4*)&hm4[r][c0] = make_float4(S[0], S[1], S[2], S[3]);
    }
    __syncthreads();

    // ---- Phase 2: vertical blur (streaming, 8-output runs) + SSIM.
    const int c  = tid & 31;
    const int r0 = (tid >> 5) * 8;   // 0..56

    u64 acc01[8], acc23[8];
    #pragma unroll
    for (int j = 0; j < 8; j++) { acc01[j] = 0; acc23[j] = 0; }

    #pragma unroll
    for (int k = 0; k < 18; k++) {
        ulonglong2 v = hmi[r0 + k][c];   // one LDS.128 feeds both moment pairs
        #pragma unroll
        for (int j = 0; j < 8; j++) {
            const int kj = k - j;
            if (kj >= 0 && kj <= 10) {
                const int wi = (kj <= 5) ? kj : 10 - kj;
                acc01[j] = f2fma(v.x, W2h[wi], acc01[j]);
                acc23[j] = f2fma(v.y, W2h[wi], acc23[j]);
            }
        }
    }

    // hm4 vertical: packed output pairs {j, j+1}
    u64 P4[4] = {0, 0, 0, 0};
    {
        float f[18];
        #pragma unroll
        for (int k = 0; k < 18; k++) f[k] = hm4[r0 + k][c];
        #pragma unroll
        for (int k = 0; k < 17; k++) {
            u64 pk = pk2(f[k], f[k + 1]);
            #pragma unroll
            for (int m = 0; m < 4; m++) {
                const int w = k - 2 * m;            // weight index for pair {2m, 2m+1}
                if (w >= 0 && w <= 10) {
                    const int wi = (w <= 5) ? w : 10 - w;
                    P4[m] = f2fma(pk, W2h[wi], P4[m]);
                }
            }
        }
    }

    float lsum = 0.f;
    const int oc = C0 + c;
    #pragma unroll
    for (int j = 0; j < 8; j++) {
        int orow = R0 + r0 + j;
        if (orow < OUT && oc < OUT) {
            float mx, my;   unpk(acc01[j], mx, my);
            float mxx, myy; unpk(acc23[j], mxx, myy);
            float p0, p1;   unpk(P4[j >> 1], p0, p1);
            float mxy = (j & 1) ? p1 : p0;
            float vx  = mxx - mx * mx;
            float vy  = myy - my * my;
            float cov = mxy - mx * my;
            float num = (2.f * mx * my + C1) * (2.f * cov + C2);
            float den = (mx * mx + my * my + C1) * (vx + vy + C2);
            lsum += __fdividef(num, den);
        }
    }

    // ---- block reduce -> global accumulator; last block finalizes + resets
    #pragma unroll
    for (int o = 16; o > 0; o >>= 1)
        lsum += __shfl_xor_sync(0xffffffffu, lsum, o);
    if ((tid & 31) == 0) red[tid >> 5] = lsum;
    __syncthreads();
    if (tid == 0) {
        float s = 0.f;
        #pragma unroll
        for (int w = 0; w < 8; w++) s += red[w];
        atomicAdd(&g_acc, (double)s);
        __threadfence();
        unsigned t = atomicInc(&g_ticket, NBLOCKS - 1);
        if (t == NBLOCKS - 1) {
            double tot = atomicAdd(&g_acc, 0.0);   // coherent read
            out[0] = (float)(1.0 - tot / NTOT);
            atomicExch((unsigned long long*)&g_acc, 0ull);  // reset for next call
        }
    }
}

extern "C" void kernel_launch(void* const* d_in, const int* in_sizes, int n_in,
                              void* d_out, int out_size) {
    const float* X = (const float*)d_in[0];
    const float* Y = (const float*)d_in[1];
    float* out = (float*)d_out;

    cudaFuncSetAttribute(ssim_main_kernel,
                         cudaFuncAttributeMaxDynamicSharedMemorySize, SMEM_B);

    dim3 grid(GX, GY, NIMG);   // 8 x 4 x 496
    ssim_main_kernel<<<grid, 256, SMEM_B>>>(X, Y, out);
}

// round 12
// speedup vs baseline: 1.0979x; 1.0192x over previous
#include <cuda_runtime.h>

// SSIM loss, single fused kernel, f32x2-packed blurs, GMEM-direct streamed
// horizontal pass, interleaved moment layout, scalar hm4 vertical.
// Shapes fixed: (16,31,256,256) fp32 x2 inputs, scalar fp32 out.

#define IMG   256
#define OUT   246          // 256 - 11 + 1
#define TW    32
#define TH    64
#define HALO  10
#define IN_H  74           // TH + HALO
#define PADI  33           // row stride (ulonglong2 elems) for interleaved moments
#define PADH  36           // row stride (floats) for hm4
#define NIMG  496
#define GX    8
#define GY    4
#define NBLOCKS (GX * GY * NIMG)   // 15872
#define NTOT  30015936.0   // 496 * 246 * 246

#define HMI_B  (IN_H * PADI * 16)            // 39072
#define HM4_B  (IN_H * PADH * 4)             // 10656
#define SMEM_B (HMI_B + HM4_B)               // 49728

typedef unsigned long long u64;

__device__ constexpr float GW[11] = {
    0.00102838f, 0.00759874f, 0.03600078f, 0.10936071f, 0.21300555f,
    0.26601174f,
    0.21300555f, 0.10936071f, 0.03600078f, 0.00759874f, 0.00102838f
};

#define C1 1.0e-4f
#define C2 9.0e-4f

// ---- packed f32x2 helpers ----
__device__ __forceinline__ u64 pk2(float x, float y) {
    u64 r; asm("mov.b64 %0, {%1, %2};" : "=l"(r) : "f"(x), "f"(y)); return r;
}
__device__ __forceinline__ void unpk(u64 p, float& x, float& y) {
    asm("mov.b64 {%0, %1}, %2;" : "=f"(x), "=f"(y) : "l"(p));
}
__device__ __forceinline__ u64 f2fma(u64 a, u64 b, u64 c) {
    u64 d; asm("fma.rn.f32x2 %0, %1, %2, %3;" : "=l"(d) : "l"(a), "l"(b), "l"(c)); return d;
}
__device__ __forceinline__ u64 f2mul(u64 a, u64 b) {
    u64 d; asm("mul.rn.f32x2 %0, %1, %2;" : "=l"(d) : "l"(a), "l"(b)); return d;
}

__device__ double   g_acc;      // zero-init; each call leaves it back at 0
__device__ unsigned g_ticket;   // wraps back to 0 every call

// 4-output horizontal run, streamed in 4 float4 chunks (only 14 of 16 taps used).
// Live state: one chunk pair (8 regs) + A/B/S accumulators (20 regs) + weights.
template<bool FAST>
__device__ __forceinline__ void hrun4(const float* __restrict__ xr,
                                      const float* __restrict__ yr,
                                      int gc, bool row_ok,
                                      u64* __restrict__ A, u64* __restrict__ B,
                                      float* __restrict__ S,
                                      const u64* __restrict__ W2h) {
    #pragma unroll
    for (int j = 0; j < 4; j++) { A[j] = 0; B[j] = 0; S[j] = 0.f; }

    #pragma unroll
    for (int q = 0; q < 4; q++) {
        float4 x4, y4;
        if (FAST) {
            if (row_ok) {
                x4 = *(const float4*)(xr + 4 * q);
                y4 = *(const float4*)(yr + 4 * q);
            } else {
                x4 = make_float4(0.f, 0.f, 0.f, 0.f);
                y4 = make_float4(0.f, 0.f, 0.f, 0.f);
            }
        } else {
            float xt[4], yt[4];
            #pragma unroll
            for (int t = 0; t < 4; t++) {
                bool ok = row_ok && (gc + 4 * q + t < IMG);
                xt[t] = ok ? xr[4 * q + t] : 0.f;
                yt[t] = ok ? yr[4 * q + t] : 0.f;
            }
            x4 = make_float4(xt[0], xt[1], xt[2], xt[3]);
            y4 = make_float4(yt[0], yt[1], yt[2], yt[3]);
        }
        const float* xs = &x4.x;
        const float* ys = &y4.x;
        #pragma unroll
        for (int t = 0; t < 4; t++) {
            const int k = 4 * q + t;
            if (k >= 14) continue;               // static prune
            float xk = xs[t], yk = ys[t];
            u64   p  = pk2(xk, yk);
            u64   sq = f2mul(p, p);
            float xy = xk * yk;
            #pragma unroll
            for (int j = 0; j < 4; j++) {
                const int kj = k - j;
                if (kj >= 0 && kj <= 10) {
                    const int wi = (kj <= 5) ? kj : 10 - kj;   // symmetry
                    A[j] = f2fma(p,  W2h[wi], A[j]);
                    B[j] = f2fma(sq, W2h[wi], B[j]);
                    S[j] = fmaf(GW[kj], xy, S[j]);             // imm-FFMA
                }
            }
        }
    }
}

__global__ __launch_bounds__(256, 4)
void ssim_main_kernel(const float* __restrict__ X, const float* __restrict__ Y,
                      float* __restrict__ out) {
    extern __shared__ __align__(16) unsigned char dsm[];
    ulonglong2 (*hmi)[PADI] = (ulonglong2(*)[PADI]) dsm;          // {.x={hx,hy}, .y={hxx,hyy}}
    float      (*hm4)[PADH] = (float     (*)[PADH])(dsm + HMI_B); // hxy
    __shared__ float red[8];

    const int tid = threadIdx.x;
    const int C0  = blockIdx.x * TW;
    const int R0  = blockIdx.y * TH;
    const int img = blockIdx.z;

    const float* __restrict__ xi = X + (size_t)img * IMG * IMG;
    const float* __restrict__ yi = Y + (size_t)img * IMG * IMG;

    // 6 distinct packed weight pairs (Gaussian symmetry: GW[k] == GW[10-k])
    u64 W2h[6];
    #pragma unroll
    for (int k = 0; k < 6; k++) W2h[k] = pk2(GW[k], GW[k]);

    // ---- Phase 1: horizontal blur from GMEM. 74 rows x 8 runs of 4 outputs.
    const bool fastcol = (C0 + 8 * 4 + 15 < IMG);  // worst run: gc = C0+28, needs +15
    for (int i = tid; i < IN_H * 8; i += 256) {
        const int r  = i >> 3;
        const int c0 = (i & 7) * 4;
        const int gr = R0 + r;
        const int gc = C0 + c0;          // multiple of 4 -> 16B aligned
        const bool row_ok = (gr < IMG);
        const float* xr = xi + gr * IMG + gc;
        const float* yr = yi + gr * IMG + gc;

        u64 A[4], B[4]; float S[4];
        if (fastcol) hrun4<true >(xr, yr, gc, row_ok, A, B, S, W2h);
        else         hrun4<false>(xr, yr, gc, row_ok, A, B, S, W2h);

        #pragma unroll
        for (int j = 0; j < 4; j++)
            hmi[r][c0 + j] = make_ulonglong2(A[j], B[j]);
        *(float4*)&hm4[r][c0] = make_float4(S[0], S[1], S[2], S[3]);
    }
    __syncthreads();

    // ---- Phase 2: vertical blur (streaming, 8-output runs) + SSIM.
    const int c  = tid & 31;
    const int r0 = (tid >> 5) * 8;   // 0..56

    u64 acc01[8], acc23[8];
    #pragma unroll
    for (int j = 0; j < 8; j++) { acc01[j] = 0; acc23[j] = 0; }

    #pragma unroll
    for (int k = 0; k < 18; k++) {
        ulonglong2 v = hmi[r0 + k][c];   // one LDS.128 feeds both moment pairs
        #pragma unroll
        for (int j = 0; j < 8; j++) {
            const int kj = k - j;
            if (kj >= 0 && kj <= 10) {
                const int wi = (kj <= 5) ? kj : 10 - kj;
                acc01[j] = f2fma(v.x, W2h[wi], acc01[j]);
                acc23[j] = f2fma(v.y, W2h[wi], acc23[j]);
            }
        }
    }

    float acc4[8];
    #pragma unroll
    for (int j = 0; j < 8; j++) acc4[j] = 0.f;
    #pragma unroll
    for (int k = 0; k < 18; k++) {
        float v = hm4[r0 + k][c];
        #pragma unroll
        for (int j = 0; j < 8; j++) {
            const int kj = k - j;
            if (kj >= 0 && kj <= 10) acc4[j] = fmaf(GW[kj], v, acc4[j]);  // imm-FFMA
        }
    }

    float lsum = 0.f;
    const int oc = C0 + c;
    #pragma unroll
    for (int j = 0; j < 8; j++) {
        int orow = R0 + r0 + j;
        if (orow < OUT && oc < OUT) {
            float mx, my;   unpk(acc01[j], mx, my);
            float mxx, myy; unpk(acc23[j], mxx, myy);
            float mxy = acc4[j];
            float vx  = mxx - mx * mx;
            float vy  = myy - my * my;
            float cov = mxy - mx * my;
            float num = (2.f * mx * my + C1) * (2.f * cov + C2);
            float den = (mx * mx + my * my + C1) * (vx + vy + C2);
            lsum += __fdividef(num, den);
        }
    }

    // ---- block reduce -> global accumulator; last block finalizes + resets
    #pragma unroll
    for (int o = 16; o > 0; o >>= 1)
        lsum += __shfl_xor_sync(0xffffffffu, lsum, o);
    if ((tid & 31) == 0) red[tid >> 5] = lsum;
    __syncthreads();
    if (tid == 0) {
        float s = 0.f;
        #pragma unroll
        for (int w = 0; w < 8; w++) s += red[w];
        atomicAdd(&g_acc, (double)s);
        __threadfence();
        unsigned t = atomicInc(&g_ticket, NBLOCKS - 1);
        if (t == NBLOCKS - 1) {
            double tot = atomicAdd(&g_acc, 0.0);   // coherent read
            out[0] = (float)(1.0 - tot / NTOT);
            atomicExch((unsigned long long*)&g_acc, 0ull);  // reset for next call
        }
    }
}

extern "C" void kernel_launch(void* const* d_in, const int* in_sizes, int n_in,
                              void* d_out, int out_size) {
    const float* X = (const float*)d_in[0];
    const float* Y = (const float*)d_in[1];
    float* out = (float*)d_out;

    cudaFuncSetAttribute(ssim_main_kernel,
                         cudaFuncAttributeMaxDynamicSharedMemorySize, SMEM_B);

    dim3 grid(GX, GY, NIMG);   // 8 x 4 x 496
    ssim_main_kernel<<<grid, 256, SMEM_B>>>(X, Y, out);
}